// round 9
// baseline (speedup 1.0000x reference)
#include <cuda_runtime.h>
#include <math.h>
#include <stdint.h>

#define Bsz 8192
#define Vn  8
#define FcN 64
#define BNEPS 1e-5f

__device__ float g_h1 [(size_t)Bsz*Vn*128];
__device__ float g_h2 [(size_t)Bsz*Vn*128];
__device__ float g_e  [(size_t)Bsz*Vn*512];
__device__ float g_hd1[(size_t)Bsz*Vn*256];
__device__ float g_hd2[(size_t)Bsz*Vn*256];
__device__ float g_HY [(size_t)Bsz*FcN*40];
__device__ float g_r1 [(size_t)Bsz*FcN*256];
__device__ float g_r2 [(size_t)Bsz*FcN*256];
__device__ float g_P   [(size_t)Bsz*Vn*32];
__device__ float g_y   [(size_t)Bsz*FcN*8];
__device__ float g_xequ[(size_t)Bsz*FcN*8];
__device__ float g_xeq1[(size_t)Bsz*FcN*8];
__device__ float g_sig [(size_t)Bsz*512];
__device__ float g_W2e[Vn*128*128]; __device__ float g_b2e[Vn*128];
__device__ float g_W3e[Vn*128*512]; __device__ float g_b3e[Vn*512];
__device__ float g_W2d[Vn*256*256]; __device__ float g_b2d[Vn*256];
__device__ float g_W3d[Vn*256*32];  __device__ float g_b3d[Vn*32];
__device__ float g_part[32*Vn*256*2];
__device__ float g_consts[4];

__device__ __forceinline__ uint32_t f2tf32(float f) {
    uint32_t r; asm("cvt.rna.tf32.f32 %0, %1;" : "=r"(r) : "f"(f)); return r;
}
__device__ __forceinline__ void mma8(float* c, const uint32_t* a, const uint32_t* b) {
    asm volatile(
        "mma.sync.aligned.m16n8k8.row.col.f32.tf32.tf32.f32 "
        "{%0,%1,%2,%3}, {%4,%5,%6,%7}, {%8,%9}, {%0,%1,%2,%3};"
        : "+f"(c[0]), "+f"(c[1]), "+f"(c[2]), "+f"(c[3])
        : "r"(a[0]), "r"(a[1]), "r"(a[2]), "r"(a[3]), "r"(b[0]), "r"(b[1]));
}

__global__ void prep_kernel(const int* __restrict__ snrp) {
    int iv = *snrp;
    float S;
    if (iv >= -1000 && iv <= 1000) S = (float)iv;
    else                            S = __int_as_float(iv);
    float snr = powf(10.f, -S * 0.1f);
    g_consts[0] = 4.f * snr;
    g_consts[1] = sqrtf(4.f * snr);
}

// ---- TF32 mma GEMM: CTA 128x128, 256 threads, warp tile 32x64 ----
// Fragment-native smem: addr(row,k) = row*16 + (k&3)*4 + (k>>2); plane 2048 u32.
template<int NTERM>
__global__ __launch_bounds__(256, 2) void mma_gemm(
    const float* __restrict__ A, int lda, long sAv,
    const float* __restrict__ W, long sWv,
    const float* __restrict__ bias, int sbv,
    float* __restrict__ C, int ldc, long sCv,
    int K, int N, int relu)
{
    extern __shared__ uint32_t smem[];
    constexpr int PL    = 2048;
    constexpr int TBUF  = (NTERM > 1) ? 2 * PL : PL;
    constexpr int B_OFF = 2 * TBUF;

    const int v = blockIdx.z;
    A    += (long)v * sAv;
    W    += (long)v * sWv;
    bias += (long)v * sbv;
    C    += (long)v * sCv;

    const long row0 = (long)blockIdx.y << 7;
    const int  col0 = blockIdx.x << 7;

    const int tid  = threadIdx.x;
    const int lane = tid & 31;
    const int wid  = tid >> 5;
    const int m0 = (wid & 3) << 5;
    const int n0 = (wid >> 2) << 6;
    const int lr = lane >> 2, lc = lane & 3;

    const int ar = tid >> 2, aq = tid & 3;          // A loader (+128 rows on it=1)
    const int kb = tid & 15, nq = tid >> 4;         // B loader (+16 nq on it=1)
    const int nch = (K + 15) >> 4;

    float4 a4[2], b4[2];

    auto load_g = [&](int k0) {
#pragma unroll
        for (int it = 0; it < 2; ++it) {
            const int r = ar + (it << 6);           // it covers rows 0..63 / 64..127
            a4[it] = make_float4(0.f, 0.f, 0.f, 0.f);
            if (4 * aq + k0 < K)
                a4[it] = *(const float4*)(A + (row0 + r) * (long)lda + k0 + 4 * aq);
            const int nn = nq + (it << 4);          // nq 0..15 / 16..31
            b4[it] = make_float4(0.f, 0.f, 0.f, 0.f);
            if ((k0 + kb < K) && (col0 + 4 * nn < N))
                b4[it] = *(const float4*)(W + (long)(k0 + kb) * N + col0 + 4 * nn);
        }
    };

    auto store_s = [&](int buf) {
        uint32_t* ab = smem + buf * TBUF;
        uint32_t* bb = smem + B_OFF + buf * TBUF;
#pragma unroll
        for (int it = 0; it < 2; ++it) {
            const int r = ar + (it << 6);
            const float* av = &a4[it].x;
#pragma unroll
            for (int t = 0; t < 4; ++t) {
                const int tt = (t + r + (r >> 2)) & 3;
                const float val = av[tt];
                const uint32_t hi = f2tf32(val);
                ab[r * 16 + tt * 4 + aq] = hi;
                if (NTERM > 1)
                    ab[PL + r * 16 + tt * 4 + aq] = f2tf32(val - __uint_as_float(hi));
            }
            const int nn = nq + (it << 4);
            const int klo = kb & 3, p = kb >> 2;
            const float* bv = &b4[it].x;
#pragma unroll
            for (int t = 0; t < 4; ++t) {
                const int tt = (t + nn) & 3;
                const int n = 4 * nn + tt;
                const float val = bv[tt];
                const uint32_t hi = f2tf32(val);
                bb[n * 16 + klo * 4 + p] = hi;
                if (NTERM > 1)
                    bb[PL + n * 16 + klo * 4 + p] = f2tf32(val - __uint_as_float(hi));
            }
        }
    };

    load_g(0);
    store_s(0);
    __syncthreads();

    float c[2][8][4] = {};
    int buf = 0;
    for (int ch = 0; ch < nch; ++ch) {
        const bool more = (ch + 1) < nch;
        if (more) load_g((ch + 1) << 4);

        const uint32_t* ab = smem + buf * TBUF;
        const uint32_t* bb = smem + B_OFF + buf * TBUF;

        uint4 AH[2][2], AL[2][2];
#pragma unroll
        for (int i = 0; i < 2; ++i) {
            const int r = m0 + i * 16 + lr;
            AH[i][0] = *(const uint4*)(ab + r * 16 + lc * 4);
            AH[i][1] = *(const uint4*)(ab + (r + 8) * 16 + lc * 4);
            if (NTERM > 1) {
                AL[i][0] = *(const uint4*)(ab + PL + r * 16 + lc * 4);
                AL[i][1] = *(const uint4*)(ab + PL + (r + 8) * 16 + lc * 4);
            }
        }
#pragma unroll
        for (int j = 0; j < 8; ++j) {
            const int n = n0 + j * 8 + lr;
            const uint4 BH = *(const uint4*)(bb + n * 16 + lc * 4);
            uint4 BL;
            if (NTERM > 1) BL = *(const uint4*)(bb + PL + n * 16 + lc * 4);
#pragma unroll
            for (int kk = 0; kk < 2; ++kk) {
                uint32_t bh[2];
                bh[0] = kk ? BH.z : BH.x;
                bh[1] = kk ? BH.w : BH.y;
#pragma unroll
                for (int i = 0; i < 2; ++i) {
                    uint32_t ah[4];
                    ah[0] = kk ? AH[i][0].z : AH[i][0].x;
                    ah[1] = kk ? AH[i][1].z : AH[i][1].x;
                    ah[2] = kk ? AH[i][0].w : AH[i][0].y;
                    ah[3] = kk ? AH[i][1].w : AH[i][1].y;
                    if (NTERM > 1) {
                        uint32_t al[4], bl[2];
                        al[0] = kk ? AL[i][0].z : AL[i][0].x;
                        al[1] = kk ? AL[i][1].z : AL[i][1].x;
                        al[2] = kk ? AL[i][0].w : AL[i][0].y;
                        al[3] = kk ? AL[i][1].w : AL[i][1].y;
                        bl[0] = kk ? BL.z : BL.x;
                        bl[1] = kk ? BL.w : BL.y;
                        mma8(c[i][j], al, bh);
                        mma8(c[i][j], ah, bl);
                    }
                    mma8(c[i][j], ah, bh);
                }
            }
        }

        if (more) store_s(buf ^ 1);
        __syncthreads();
        buf ^= 1;
    }

#pragma unroll
    for (int i = 0; i < 2; ++i) {
        const long r0e = row0 + m0 + i * 16 + lr;
#pragma unroll
        for (int j = 0; j < 8; ++j) {
            const int col = col0 + n0 + j * 8 + lc * 2;
            if (col < N) {
                const float2 bv = *(const float2*)(bias + col);
                float v0 = c[i][j][0] + bv.x;
                float v1 = c[i][j][1] + bv.y;
                float v2 = c[i][j][2] + bv.x;
                float v3 = c[i][j][3] + bv.y;
                if (relu) {
                    v0 = fmaxf(v0, 0.f); v1 = fmaxf(v1, 0.f);
                    v2 = fmaxf(v2, 0.f); v3 = fmaxf(v3, 0.f);
                }
                float2 o0 = {v0, v1}, o1 = {v2, v3};
                *(float2*)(C + r0e * (long)ldc + col)       = o0;
                *(float2*)(C + (r0e + 8) * (long)ldc + col) = o1;
            }
        }
    }
}

__global__ void stats_kernel(const float* __restrict__ h, int C, float* __restrict__ part) {
    const int v = blockIdx.x, s = blockIdx.y, c = threadIdx.x;
    const long stride = (long)Vn * C;
    const float* p = h + ((long)(s * 256) * Vn + v) * C + c;
    float sum = 0.f, sq = 0.f;
#pragma unroll 4
    for (int i = 0; i < 256; ++i) {
        float val = p[(long)i * stride];
        sum += val;
        sq = fmaf(val, val, sq);
    }
    const long o = (((long)s * Vn + v) * C + c) * 2;
    part[o] = sum; part[o + 1] = sq;
}

__global__ void fuse_kernel(const float* __restrict__ W, const float* __restrict__ bias,
                            const float* __restrict__ g, const float* __restrict__ be,
                            int Cin, int Nout,
                            float* __restrict__ Wp, float* __restrict__ bp)
{
    const int v = blockIdx.x, tid = threadIdx.x;
    __shared__ float sa[512], sc[512];
    for (int n = tid; n < Cin; n += blockDim.x) {
        float sum = 0.f, sq = 0.f;
        for (int s = 0; s < 32; ++s) {
            const long o = (((long)s * Vn + v) * Cin + n) * 2;
            sum += g_part[o]; sq += g_part[o + 1];
        }
        const float mu  = sum * (1.f / Bsz);
        const float var = sq * (1.f / Bsz) - mu * mu;
        const float rs  = rsqrtf(var + BNEPS);
        const float a   = g[v * Cin + n] * rs;
        sa[n] = a;
        sc[n] = be[v * Cin + n] - mu * a;
    }
    __syncthreads();
    const float* wv = W + (long)v * Cin * Nout;
    float* wpv = Wp + (long)v * Cin * Nout;
    for (int j = tid; j < Nout; j += blockDim.x) {
        float acc = bias[v * Nout + j];
        for (int n = 0; n < Cin; ++n) {
            const float w = wv[(long)n * Nout + j];
            wpv[(long)n * Nout + j] = sa[n] * w;
            acc = fmaf(sc[n], w, acc);
        }
        bp[v * Nout + j] = acc;
    }
}

__global__ void combine_kernel(float* __restrict__ enc_sig) {
    const int b = blockIdx.x;
    const int d = threadIdx.x;
    __shared__ float red[16];
    __shared__ float tot_s;
    float acc = 0.f;
#pragma unroll
    for (int v = 0; v < Vn; ++v) {
        const float ev = g_e[((long)b * Vn + v) * 512 + d];
        float s = ev * ev;
#pragma unroll
        for (int o = 16; o; o >>= 1) s += __shfl_xor_sync(0xffffffffu, s, o);
        if ((d & 31) == 0) red[d >> 5] = s;
        __syncthreads();
        if (d < 32) {
            float t = (d < 16) ? red[d] : 0.f;
#pragma unroll
            for (int o = 8; o; o >>= 1) t += __shfl_xor_sync(0xffffffffu, t, o);
            if (d == 0) tot_s = t;
        }
        __syncthreads();
        const float alpha = 8.f * rsqrtf(tot_s);
        acc = fmaf(alpha, ev, acc);
        __syncthreads();
    }
    enc_sig[(long)b * 512 + d] = acc * 0.70710678118654752f;
}

struct C2 { float x, y; };
__device__ __forceinline__ C2 cmul(C2 a, C2 b) { return {a.x*b.x - a.y*b.y, a.x*b.y + a.y*b.x}; }
__device__ __forceinline__ C2 cmulc(C2 a, C2 b) { return {a.x*b.x + a.y*b.y, a.x*b.y - a.y*b.x}; }

__global__ void channel_kernel(const float* __restrict__ Hri, const float* __restrict__ noiseri,
                               const float* __restrict__ encsig,
                               float* __restrict__ yout, float* __restrict__ xeq1out)
{
    const int b = blockIdx.x;
    const int f = threadIdx.x;
    __shared__ C2 H[4][4];
    __shared__ C2 Ainv[4][4];
    const float is2 = 0.70710678118654752f;

    if (f < 16) {
        const int r = f >> 2, t = f & 3;
        const long o = (((long)(b * 4 + r)) * 4 + t) * 2;
        H[r][t] = {Hri[o] * is2, Hri[o + 1] * is2};
    }
    __syncthreads();

    const float lam = g_consts[0];
    const float nsc = g_consts[1];

    if (f == 0) {
        C2 Am[4][8];
        for (int i = 0; i < 4; ++i) {
            for (int j = 0; j < 4; ++j) {
                C2 a = {0.f, 0.f};
                for (int r = 0; r < 4; ++r) {
                    C2 p = cmulc(H[r][i], H[r][j]);
                    a.x += p.x; a.y += p.y;
                }
                if (i == j) a.x += lam;
                Am[i][j] = a;
                Am[i][4 + j] = (i == j) ? C2{1.f, 0.f} : C2{0.f, 0.f};
            }
        }
        for (int p = 0; p < 4; ++p) {
            C2 dg = Am[p][p];
            const float inv = 1.f / (dg.x * dg.x + dg.y * dg.y);
            const C2 dinv = {dg.x * inv, -dg.y * inv};
            for (int j = 0; j < 8; ++j) Am[p][j] = cmul(Am[p][j], dinv);
            for (int r = 0; r < 4; ++r) {
                if (r == p) continue;
                const C2 fac = Am[r][p];
                for (int j = 0; j < 8; ++j) {
                    const C2 q = cmul(fac, Am[p][j]);
                    Am[r][j].x -= q.x; Am[r][j].y -= q.y;
                }
            }
        }
        for (int i = 0; i < 4; ++i)
            for (int j = 0; j < 4; ++j)
                Ainv[i][j] = Am[i][4 + j];
    }
    __syncthreads();

    C2 s[4];
#pragma unroll
    for (int t = 0; t < 4; ++t) {
        const long o = ((long)b * 512) + ((long)(f * 4 + t)) * 2;
        s[t] = {encsig[o], encsig[o + 1]};
    }
    const long nbase = ((long)(b * 64 + f)) * 8;
    C2 yv[4];
#pragma unroll
    for (int r = 0; r < 4; ++r) {
        C2 a = {0.f, 0.f};
#pragma unroll
        for (int t = 0; t < 4; ++t) { C2 p = cmul(H[r][t], s[t]); a.x += p.x; a.y += p.y; }
        a.x += nsc * noiseri[nbase + r * 2]     * is2;
        a.y += nsc * noiseri[nbase + r * 2 + 1] * is2;
        yv[r] = a;
        yout[nbase + r * 2]     = a.x;
        yout[nbase + r * 2 + 1] = a.y;
    }
    C2 hy[4];
#pragma unroll
    for (int t = 0; t < 4; ++t) {
        C2 a = {0.f, 0.f};
#pragma unroll
        for (int r = 0; r < 4; ++r) { C2 p = cmulc(H[r][t], yv[r]); a.x += p.x; a.y += p.y; }
        hy[t] = a;
    }
#pragma unroll
    for (int t = 0; t < 4; ++t) {
        C2 a = {0.f, 0.f};
#pragma unroll
        for (int k = 0; k < 4; ++k) { C2 p = cmul(Ainv[t][k], hy[k]); a.x += p.x; a.y += p.y; }
        xeq1out[nbase + t * 2]     = a.x;
        xeq1out[nbase + t * 2 + 1] = a.y;
    }
    float* hyp = &g_HY[((long)(b * 64 + f)) * 40];
#pragma unroll
    for (int r = 0; r < 4; ++r)
#pragma unroll
        for (int t = 0; t < 4; ++t) {
            hyp[(r * 4 + t) * 2]     = H[r][t].x;
            hyp[(r * 4 + t) * 2 + 1] = H[r][t].y;
        }
#pragma unroll
    for (int r = 0; r < 4; ++r) {
        hyp[32 + r * 2]     = yv[r].x;
        hyp[32 + r * 2 + 1] = yv[r].y;
    }
}

__global__ __launch_bounds__(256) void res3_add_kernel(
    const float* __restrict__ r2, const float* __restrict__ W3,
    const float* __restrict__ b3, const float* __restrict__ xeq1,
    float* __restrict__ xequ)
{
    __shared__ float wt[8][256];
    __shared__ float bs[8];
    const int tid = threadIdx.x;
    if (tid < 8) bs[tid] = b3[tid];
#pragma unroll
    for (int j = 0; j < 8; ++j)
        wt[j][tid] = W3[tid * 8 + j];
    __syncthreads();

    const int warp = tid >> 5, lane = tid & 31;
    const long row = (long)blockIdx.x * 8 + warp;
    const float* rp = r2 + row * 256;
    float acc[8] = {};
#pragma unroll
    for (int ii = 0; ii < 8; ++ii) {
        const int i = ii * 32 + lane;
        const float rv = rp[i];
#pragma unroll
        for (int j = 0; j < 8; ++j) acc[j] = fmaf(rv, wt[j][i], acc[j]);
    }
#pragma unroll
    for (int j = 0; j < 8; ++j)
#pragma unroll
        for (int o = 16; o; o >>= 1) acc[j] += __shfl_xor_sync(0xffffffffu, acc[j], o);
    if (lane == 0) {
        const long ob = row * 8;
#pragma unroll
        for (int j = 0; j < 8; ++j)
            xequ[ob + j] = xeq1[ob + j] + acc[j] + bs[j];
    }
}

__global__ void emit_kernel(const float* __restrict__ src, float* __restrict__ out,
                            long off, long n, long out_size, int mode) {
    const long i = (long)blockIdx.x * blockDim.x + threadIdx.x;
    if (i >= n) return;
    const long o = off + i;
    if (o >= out_size) return;
    out[o] = (mode == 0) ? src[i] : src[2 * i];
}

extern "C" void kernel_launch(void* const* d_in, const int* in_sizes, int n_in,
                              void* d_out, int out_size) {
    const float* x        = (const float*)d_in[0];
    const int*   snr      = (const int*)  d_in[1];
    const float* H_ri     = (const float*)d_in[2];
    const float* noise_ri = (const float*)d_in[3];
    const float* enc_W1 = (const float*)d_in[4];  const float* enc_b1 = (const float*)d_in[5];
    const float* enc_g1 = (const float*)d_in[6];  const float* enc_be1= (const float*)d_in[7];
    const float* enc_W2 = (const float*)d_in[8];  const float* enc_b2 = (const float*)d_in[9];
    const float* enc_g2 = (const float*)d_in[10]; const float* enc_be2= (const float*)d_in[11];
    const float* enc_W3 = (const float*)d_in[12]; const float* enc_b3 = (const float*)d_in[13];
    const float* dec_W1 = (const float*)d_in[14]; const float* dec_b1 = (const float*)d_in[15];
    const float* dec_g1 = (const float*)d_in[16]; const float* dec_be1= (const float*)d_in[17];
    const float* dec_W2 = (const float*)d_in[18]; const float* dec_b2 = (const float*)d_in[19];
    const float* dec_g2 = (const float*)d_in[20]; const float* dec_be2= (const float*)d_in[21];
    const float* dec_W3 = (const float*)d_in[22]; const float* dec_b3 = (const float*)d_in[23];
    const float* res_W1 = (const float*)d_in[24]; const float* res_b1 = (const float*)d_in[25];
    const float* res_W2 = (const float*)d_in[26]; const float* res_b2 = (const float*)d_in[27];
    const float* res_W3 = (const float*)d_in[28]; const float* res_b3 = (const float*)d_in[29];

    float *h1, *h2, *e, *hd1, *hd2, *HY, *r1, *r2;
    float *P, *y, *xequ, *xeq1, *sig;
    float *W2e, *b2e, *W3e, *b3e, *W2d, *b2d, *W3d, *b3d, *part;
    cudaGetSymbolAddress((void**)&h1,  g_h1);
    cudaGetSymbolAddress((void**)&h2,  g_h2);
    cudaGetSymbolAddress((void**)&e,   g_e);
    cudaGetSymbolAddress((void**)&hd1, g_hd1);
    cudaGetSymbolAddress((void**)&hd2, g_hd2);
    cudaGetSymbolAddress((void**)&HY,  g_HY);
    cudaGetSymbolAddress((void**)&r1,  g_r1);
    cudaGetSymbolAddress((void**)&r2,  g_r2);
    cudaGetSymbolAddress((void**)&P,    g_P);
    cudaGetSymbolAddress((void**)&y,    g_y);
    cudaGetSymbolAddress((void**)&xequ, g_xequ);
    cudaGetSymbolAddress((void**)&xeq1, g_xeq1);
    cudaGetSymbolAddress((void**)&sig,  g_sig);
    cudaGetSymbolAddress((void**)&W2e, g_W2e); cudaGetSymbolAddress((void**)&b2e, g_b2e);
    cudaGetSymbolAddress((void**)&W3e, g_W3e); cudaGetSymbolAddress((void**)&b3e, g_b3e);
    cudaGetSymbolAddress((void**)&W2d, g_W2d); cudaGetSymbolAddress((void**)&b2d, g_b2d);
    cudaGetSymbolAddress((void**)&W3d, g_W3d); cudaGetSymbolAddress((void**)&b3d, g_b3d);
    cudaGetSymbolAddress((void**)&part, g_part);

    const int SMB3 = 16384 * 4;  // 65536 B (2 A + 2 B buffers, hi+lo planes)
    const int SMB1 = 8192 * 4;   // 32768 B
    cudaFuncSetAttribute(mma_gemm<3>, cudaFuncAttributeMaxDynamicSharedMemorySize, SMB3);
    cudaFuncSetAttribute(mma_gemm<1>, cudaFuncAttributeMaxDynamicSharedMemorySize, SMB1);

    prep_kernel<<<1, 1>>>(snr);

    // ---- encoder (3xTF32) ----
    mma_gemm<3><<<dim3(1, 64, 8), 256, SMB3>>>(x, 256, 32, enc_W1, 32 * 128, enc_b1, 128,
                                               h1, 1024, 128, 32, 128, 1);
    stats_kernel<<<dim3(8, 32), 128>>>(h1, 128, part);
    fuse_kernel<<<8, 256>>>(enc_W2, enc_b2, enc_g1, enc_be1, 128, 128, W2e, b2e);
    mma_gemm<3><<<dim3(1, 64, 8), 256, SMB3>>>(h1, 1024, 128, W2e, 128 * 128, b2e, 128,
                                               h2, 1024, 128, 128, 128, 1);
    stats_kernel<<<dim3(8, 32), 128>>>(h2, 128, part);
    fuse_kernel<<<8, 256>>>(enc_W3, enc_b3, enc_g2, enc_be2, 128, 512, W3e, b3e);
    mma_gemm<3><<<dim3(4, 64, 8), 256, SMB3>>>(h2, 1024, 128, W3e, 128 * 512, b3e, 512,
                                               e, 4096, 512, 128, 512, 0);
    combine_kernel<<<8192, 512>>>(sig);

    // ---- channel + MMSE ----
    channel_kernel<<<8192, 64>>>(H_ri, noise_ri, sig, y, xeq1);

    // ---- residual MLP (1xTF32) ----
    mma_gemm<1><<<dim3(2, 4096, 1), 256, SMB1>>>(HY, 40, 0, res_W1, 0, res_b1, 0,
                                                 r1, 256, 0, 40, 256, 1);
    mma_gemm<1><<<dim3(2, 4096, 1), 256, SMB1>>>(r1, 256, 0, res_W2, 0, res_b2, 0,
                                                 r2, 256, 0, 256, 256, 1);
    res3_add_kernel<<<65536, 256>>>(r2, res_W3, res_b3, xeq1, xequ);

    // ---- decoder (dec1/dec2 3xTF32, dec3 1xTF32) ----
    mma_gemm<3><<<dim3(2, 64, 8), 256, SMB3>>>(xequ, 512, 0, dec_W1, 512 * 256, dec_b1, 256,
                                               hd1, 2048, 256, 512, 256, 1);
    stats_kernel<<<dim3(8, 32), 256>>>(hd1, 256, part);
    fuse_kernel<<<8, 256>>>(dec_W2, dec_b2, dec_g1, dec_be1, 256, 256, W2d, b2d);
    mma_gemm<3><<<dim3(2, 64, 8), 256, SMB3>>>(hd1, 2048, 256, W2d, 256 * 256, b2d, 256,
                                               hd2, 2048, 256, 256, 256, 1);
    stats_kernel<<<dim3(8, 32), 256>>>(hd2, 256, part);
    fuse_kernel<<<8, 256>>>(dec_W3, dec_b3, dec_g2, dec_be2, 256, 32, W3d, b3d);
    mma_gemm<1><<<dim3(1, 64, 8), 256, SMB1>>>(hd2, 2048, 256, W3d, 256 * 32, b3d, 32,
                                               P, 256, 32, 256, 32, 0);

    // ---- emission ----
    float* out = (float*)d_out;
    const long LP = 2097152, LY = 4194304, LX = 4194304, LS = 4194304;
    const long osz = (long)out_size;
    auto emit = [&](const float* src, long off, long n, int mode) {
        if (off >= osz || n <= 0) return;
        long grid = (n + 255) / 256;
        emit_kernel<<<(unsigned)grid, 256>>>(src, out, off, n, osz, mode);
    };
    if (osz == LP + LY/2 + LX + LX + LS) {
        long off = 0;
        emit(P,    off, LP,   0); off += LP;
        emit(y,    off, LY/2, 1); off += LY/2;
        emit(xequ, off, LX,   0); off += LX;
        emit(xeq1, off, LX,   0); off += LX;
        emit(sig,  off, LS,   0);
    } else {
        long off = 0;
        emit(P,    off, LP, 0); off += LP;
        emit(y,    off, LY, 0); off += LY;
        emit(xequ, off, LX, 0); off += LX;
        emit(xeq1, off, LX, 0); off += LX;
        emit(sig,  off, LS, 0);
    }
}

// round 10
// speedup vs baseline: 1.2153x; 1.2153x over previous
#include <cuda_runtime.h>
#include <math.h>
#include <stdint.h>

#define Bsz 8192
#define Vn  8
#define FcN 64
#define BNEPS 1e-5f

__device__ float g_h1 [(size_t)Bsz*Vn*128];
__device__ float g_h2 [(size_t)Bsz*Vn*128];
__device__ float g_e  [(size_t)Bsz*Vn*512];
__device__ float g_hd1[(size_t)Bsz*Vn*256];
__device__ float g_hd2[(size_t)Bsz*Vn*256];
__device__ float g_HY [(size_t)Bsz*FcN*40];
__device__ float g_r1 [(size_t)Bsz*FcN*256];
__device__ float g_r2 [(size_t)Bsz*FcN*256];
__device__ float g_P   [(size_t)Bsz*Vn*32];
__device__ float g_y   [(size_t)Bsz*FcN*8];
__device__ float g_xequ[(size_t)Bsz*FcN*8];
__device__ float g_xeq1[(size_t)Bsz*FcN*8];
__device__ float g_sig [(size_t)Bsz*512];
__device__ float g_W2e[Vn*128*128]; __device__ float g_b2e[Vn*128];
__device__ float g_W3e[Vn*128*512]; __device__ float g_b3e[Vn*512];
__device__ float g_W2d[Vn*256*256]; __device__ float g_b2d[Vn*256];
__device__ float g_W3d[Vn*256*32];  __device__ float g_b3d[Vn*32];
__device__ float g_part[32*Vn*256*2];
__device__ float g_consts[4];

__device__ __forceinline__ uint32_t f2tf32(float f) {
    uint32_t r; asm("cvt.rna.tf32.f32 %0, %1;" : "=r"(r) : "f"(f)); return r;
}
__device__ __forceinline__ void split_tf32(float f, uint32_t& hi, uint32_t& lo) {
    hi = f2tf32(f);
    lo = f2tf32(f - __uint_as_float(hi));
}
__device__ __forceinline__ void mma8(float* c, const uint32_t* a, const uint32_t* b) {
    asm volatile(
        "mma.sync.aligned.m16n8k8.row.col.f32.tf32.tf32.f32 "
        "{%0,%1,%2,%3}, {%4,%5,%6,%7}, {%8,%9}, {%0,%1,%2,%3};"
        : "+f"(c[0]), "+f"(c[1]), "+f"(c[2]), "+f"(c[3])
        : "r"(a[0]), "r"(a[1]), "r"(a[2]), "r"(a[3]), "r"(b[0]), "r"(b[1]));
}

__global__ void prep_kernel(const int* __restrict__ snrp) {
    int iv = *snrp;
    float S;
    if (iv >= -1000 && iv <= 1000) S = (float)iv;
    else                            S = __int_as_float(iv);
    float snr = powf(10.f, -S * 0.1f);
    g_consts[0] = 4.f * snr;
    g_consts[1] = sqrtf(4.f * snr);
}

// ---- TF32 mma GEMM (round-7 proven design): CTA 128x128, 512 thr, warp 32x32 ----
#define AST 20
#define BST 136
#define AS_SZ   (128 * AST)
#define BS_SZ   (16 * BST)

template<int NTERM>
__global__ __launch_bounds__(512) void mma_gemm(
    const float* __restrict__ A, int lda, long sAv,
    const float* __restrict__ W, long sWv,
    const float* __restrict__ bias, int sbv,
    float* __restrict__ C, int ldc, long sCv,
    int K, int N, int relu)
{
    extern __shared__ uint32_t smem[];
    constexpr int A_BUF   = (NTERM > 1) ? 2 * AS_SZ : AS_SZ;
    constexpr int B_BUF   = (NTERM > 1) ? 2 * BS_SZ : BS_SZ;
    constexpr int BS_BASE = 2 * A_BUF;

    const int v = blockIdx.z;
    A    += (long)v * sAv;
    W    += (long)v * sWv;
    bias += (long)v * sbv;
    C    += (long)v * sCv;

    const long row0 = (long)blockIdx.y << 7;
    const int  col0 = blockIdx.x << 7;

    const int tid  = threadIdx.x;
    const int lane = tid & 31;
    const int wid  = tid >> 5;
    const int m0 = (wid & 3) << 5;
    const int n0 = (wid >> 2) << 5;

    const int ar  = tid >> 2;
    const int akq = (tid & 3) << 2;
    const int bk  = tid >> 5;
    const int bnq = (tid & 15) << 3 | ((tid >> 4) & 1) << 2;  // same coverage as (tid&31)<<2
    const bool bok = (col0 + bnq) < N;

    const float* Ap = A + (row0 + ar) * (long)lda;
    const float* Wp = W + (long)col0 + bnq;

    const int nch = (K + 15) >> 4;

    auto store_tiles = [&](int nb, float4 a4, float4 b4) {
        uint32_t* ash = smem + nb * A_BUF + ar * AST + akq;
        uint32_t* bsh = smem + BS_BASE + nb * B_BUF + bk * BST + bnq;
        if (NTERM > 1) {
            uint32_t* asl = ash + AS_SZ;
            split_tf32(a4.x, ash[0], asl[0]); split_tf32(a4.y, ash[1], asl[1]);
            split_tf32(a4.z, ash[2], asl[2]); split_tf32(a4.w, ash[3], asl[3]);
            uint32_t* bsl = bsh + BS_SZ;
            split_tf32(b4.x, bsh[0], bsl[0]); split_tf32(b4.y, bsh[1], bsl[1]);
            split_tf32(b4.z, bsh[2], bsl[2]); split_tf32(b4.w, bsh[3], bsl[3]);
        } else {
            ash[0] = f2tf32(a4.x); ash[1] = f2tf32(a4.y);
            ash[2] = f2tf32(a4.z); ash[3] = f2tf32(a4.w);
            bsh[0] = f2tf32(b4.x); bsh[1] = f2tf32(b4.y);
            bsh[2] = f2tf32(b4.z); bsh[3] = f2tf32(b4.w);
        }
    };

    {
        float4 a4 = make_float4(0.f, 0.f, 0.f, 0.f);
        if (akq < K) a4 = *(const float4*)(Ap + akq);
        float4 b4 = make_float4(0.f, 0.f, 0.f, 0.f);
        if (bok && bk < K) b4 = *(const float4*)(Wp + (long)bk * N);
        store_tiles(0, a4, b4);
    }
    __syncthreads();

    float c[2][4][4] = {};
    int buf = 0;
    for (int ch = 0; ch < nch; ++ch) {
        float4 a4 = make_float4(0.f, 0.f, 0.f, 0.f);
        float4 b4 = make_float4(0.f, 0.f, 0.f, 0.f);
        const int nk0 = (ch + 1) << 4;
        const bool more = (ch + 1) < nch;
        if (more) {
            if (nk0 + akq < K) a4 = *(const float4*)(Ap + nk0 + akq);
            if (bok && (nk0 + bk) < K) b4 = *(const float4*)(Wp + (long)(nk0 + bk) * N);
        }

        const uint32_t* asb = smem + buf * A_BUF + (m0 + (lane >> 2)) * AST + (lane & 3);
        const uint32_t* bsb = smem + BS_BASE + buf * B_BUF + (lane & 3) * BST + n0 + (lane >> 2);
#pragma unroll
        for (int kk = 0; kk < 2; ++kk) {
            uint32_t ah[2][4], al[2][4];
#pragma unroll
            for (int i = 0; i < 2; ++i) {
                const uint32_t* p = asb + (i << 4) * AST + (kk << 3);
                ah[i][0] = p[0];
                ah[i][1] = p[8 * AST];
                ah[i][2] = p[4];
                ah[i][3] = p[8 * AST + 4];
                if (NTERM > 1) {
                    const uint32_t* pl = p + AS_SZ;
                    al[i][0] = pl[0];
                    al[i][1] = pl[8 * AST];
                    al[i][2] = pl[4];
                    al[i][3] = pl[8 * AST + 4];
                }
            }
            uint32_t bh[4][2], bl[4][2];
#pragma unroll
            for (int j = 0; j < 4; ++j) {
                const uint32_t* q = bsb + (kk << 3) * BST + (j << 3);
                bh[j][0] = q[0];
                bh[j][1] = q[4 * BST];
                if (NTERM > 1) {
                    const uint32_t* ql = q + BS_SZ;
                    bl[j][0] = ql[0];
                    bl[j][1] = ql[4 * BST];
                }
            }
#pragma unroll
            for (int i = 0; i < 2; ++i)
#pragma unroll
                for (int j = 0; j < 4; ++j) {
                    if (NTERM > 1) {
                        mma8(c[i][j], al[i], bh[j]);
                        mma8(c[i][j], ah[i], bl[j]);
                    }
                    mma8(c[i][j], ah[i], bh[j]);
                }
        }

        if (more) store_tiles(buf ^ 1, a4, b4);
        __syncthreads();
        buf ^= 1;
    }

#pragma unroll
    for (int i = 0; i < 2; ++i) {
        const long row = row0 + m0 + (i << 4) + (lane >> 2);
#pragma unroll
        for (int j = 0; j < 4; ++j) {
            const int col = col0 + n0 + (j << 3) + ((lane & 3) << 1);
            if (col < N) {
                const float2 bv = *(const float2*)(bias + col);
                float v0 = c[i][j][0] + bv.x;
                float v1 = c[i][j][1] + bv.y;
                float v2 = c[i][j][2] + bv.x;
                float v3 = c[i][j][3] + bv.y;
                if (relu) {
                    v0 = fmaxf(v0, 0.f); v1 = fmaxf(v1, 0.f);
                    v2 = fmaxf(v2, 0.f); v3 = fmaxf(v3, 0.f);
                }
                float2 o0 = {v0, v1}, o1 = {v2, v3};
                *(float2*)(C + row * (long)ldc + col)       = o0;
                *(float2*)(C + (row + 8) * (long)ldc + col) = o1;
            }
        }
    }
}

__global__ void stats_kernel(const float* __restrict__ h, int C, float* __restrict__ part) {
    const int v = blockIdx.x, s = blockIdx.y, c = threadIdx.x;
    const long stride = (long)Vn * C;
    const float* p = h + ((long)(s * 256) * Vn + v) * C + c;
    float sum = 0.f, sq = 0.f;
#pragma unroll 4
    for (int i = 0; i < 256; ++i) {
        float val = p[(long)i * stride];
        sum += val;
        sq = fmaf(val, val, sq);
    }
    const long o = (((long)s * Vn + v) * C + c) * 2;
    part[o] = sum; part[o + 1] = sq;
}

// fold BN into next layer; grid (Vn, JB) — each block handles a slice of Nout
__global__ void fuse_kernel(const float* __restrict__ W, const float* __restrict__ bias,
                            const float* __restrict__ g, const float* __restrict__ be,
                            int Cin, int Nout,
                            float* __restrict__ Wp, float* __restrict__ bp)
{
    const int v = blockIdx.x, tid = threadIdx.x;
    __shared__ float sa[512], sc[512];
    for (int n = tid; n < Cin; n += blockDim.x) {
        float sum = 0.f, sq = 0.f;
        for (int s = 0; s < 32; ++s) {
            const long o = (((long)s * Vn + v) * Cin + n) * 2;
            sum += g_part[o]; sq += g_part[o + 1];
        }
        const float mu  = sum * (1.f / Bsz);
        const float var = sq * (1.f / Bsz) - mu * mu;
        const float rs  = rsqrtf(var + BNEPS);
        const float a   = g[v * Cin + n] * rs;
        sa[n] = a;
        sc[n] = be[v * Cin + n] - mu * a;
    }
    __syncthreads();
    const int slice = (Nout + gridDim.y - 1) / gridDim.y;
    const int j0 = blockIdx.y * slice;
    const int j1 = min(j0 + slice, Nout);
    const float* wv = W + (long)v * Cin * Nout;
    float* wpv = Wp + (long)v * Cin * Nout;
    for (int j = j0 + tid; j < j1; j += blockDim.x) {
        float acc = bias[v * Nout + j];
        for (int n = 0; n < Cin; ++n) {
            const float w = wv[(long)n * Nout + j];
            wpv[(long)n * Nout + j] = sa[n] * w;
            acc = fmaf(sc[n], w, acc);
        }
        bp[v * Nout + j] = acc;
    }
}

__global__ void combine_kernel(float* __restrict__ enc_sig) {
    const int b = blockIdx.x;
    const int d = threadIdx.x;
    __shared__ float red[16];
    __shared__ float tot_s;
    float acc = 0.f;
#pragma unroll
    for (int v = 0; v < Vn; ++v) {
        const float ev = g_e[((long)b * Vn + v) * 512 + d];
        float s = ev * ev;
#pragma unroll
        for (int o = 16; o; o >>= 1) s += __shfl_xor_sync(0xffffffffu, s, o);
        if ((d & 31) == 0) red[d >> 5] = s;
        __syncthreads();
        if (d < 32) {
            float t = (d < 16) ? red[d] : 0.f;
#pragma unroll
            for (int o = 8; o; o >>= 1) t += __shfl_xor_sync(0xffffffffu, t, o);
            if (d == 0) tot_s = t;
        }
        __syncthreads();
        const float alpha = 8.f * rsqrtf(tot_s);
        acc = fmaf(alpha, ev, acc);
        __syncthreads();
    }
    enc_sig[(long)b * 512 + d] = acc * 0.70710678118654752f;
}

struct C2 { float x, y; };
__device__ __forceinline__ C2 cmul(C2 a, C2 b) { return {a.x*b.x - a.y*b.y, a.x*b.y + a.y*b.x}; }
__device__ __forceinline__ C2 cmulc(C2 a, C2 b) { return {a.x*b.x + a.y*b.y, a.x*b.y - a.y*b.x}; }

__global__ void channel_kernel(const float* __restrict__ Hri, const float* __restrict__ noiseri,
                               const float* __restrict__ encsig,
                               float* __restrict__ yout, float* __restrict__ xeq1out)
{
    const int b = blockIdx.x;
    const int f = threadIdx.x;
    __shared__ C2 H[4][4];
    __shared__ C2 Ainv[4][4];
    const float is2 = 0.70710678118654752f;

    if (f < 16) {
        const int r = f >> 2, t = f & 3;
        const long o = (((long)(b * 4 + r)) * 4 + t) * 2;
        H[r][t] = {Hri[o] * is2, Hri[o + 1] * is2};
    }
    __syncthreads();

    const float lam = g_consts[0];
    const float nsc = g_consts[1];

    if (f == 0) {
        C2 Am[4][8];
        for (int i = 0; i < 4; ++i) {
            for (int j = 0; j < 4; ++j) {
                C2 a = {0.f, 0.f};
                for (int r = 0; r < 4; ++r) {
                    C2 p = cmulc(H[r][i], H[r][j]);
                    a.x += p.x; a.y += p.y;
                }
                if (i == j) a.x += lam;
                Am[i][j] = a;
                Am[i][4 + j] = (i == j) ? C2{1.f, 0.f} : C2{0.f, 0.f};
            }
        }
        for (int p = 0; p < 4; ++p) {
            C2 dg = Am[p][p];
            const float inv = 1.f / (dg.x * dg.x + dg.y * dg.y);
            const C2 dinv = {dg.x * inv, -dg.y * inv};
            for (int j = 0; j < 8; ++j) Am[p][j] = cmul(Am[p][j], dinv);
            for (int r = 0; r < 4; ++r) {
                if (r == p) continue;
                const C2 fac = Am[r][p];
                for (int j = 0; j < 8; ++j) {
                    const C2 q = cmul(fac, Am[p][j]);
                    Am[r][j].x -= q.x; Am[r][j].y -= q.y;
                }
            }
        }
        for (int i = 0; i < 4; ++i)
            for (int j = 0; j < 4; ++j)
                Ainv[i][j] = Am[i][4 + j];
    }
    __syncthreads();

    C2 s[4];
#pragma unroll
    for (int t = 0; t < 4; ++t) {
        const long o = ((long)b * 512) + ((long)(f * 4 + t)) * 2;
        s[t] = {encsig[o], encsig[o + 1]};
    }
    const long nbase = ((long)(b * 64 + f)) * 8;
    C2 yv[4];
#pragma unroll
    for (int r = 0; r < 4; ++r) {
        C2 a = {0.f, 0.f};
#pragma unroll
        for (int t = 0; t < 4; ++t) { C2 p = cmul(H[r][t], s[t]); a.x += p.x; a.y += p.y; }
        a.x += nsc * noiseri[nbase + r * 2]     * is2;
        a.y += nsc * noiseri[nbase + r * 2 + 1] * is2;
        yv[r] = a;
        yout[nbase + r * 2]     = a.x;
        yout[nbase + r * 2 + 1] = a.y;
    }
    C2 hy[4];
#pragma unroll
    for (int t = 0; t < 4; ++t) {
        C2 a = {0.f, 0.f};
#pragma unroll
        for (int r = 0; r < 4; ++r) { C2 p = cmulc(H[r][t], yv[r]); a.x += p.x; a.y += p.y; }
        hy[t] = a;
    }
#pragma unroll
    for (int t = 0; t < 4; ++t) {
        C2 a = {0.f, 0.f};
#pragma unroll
        for (int k = 0; k < 4; ++k) { C2 p = cmul(Ainv[t][k], hy[k]); a.x += p.x; a.y += p.y; }
        xeq1out[nbase + t * 2]     = a.x;
        xeq1out[nbase + t * 2 + 1] = a.y;
    }
    float* hyp = &g_HY[((long)(b * 64 + f)) * 40];
#pragma unroll
    for (int r = 0; r < 4; ++r)
#pragma unroll
        for (int t = 0; t < 4; ++t) {
            hyp[(r * 4 + t) * 2]     = H[r][t].x;
            hyp[(r * 4 + t) * 2 + 1] = H[r][t].y;
        }
#pragma unroll
    for (int r = 0; r < 4; ++r) {
        hyp[32 + r * 2]     = yv[r].x;
        hyp[32 + r * 2 + 1] = yv[r].y;
    }
}

__global__ __launch_bounds__(256) void res3_add_kernel(
    const float* __restrict__ r2, const float* __restrict__ W3,
    const float* __restrict__ b3, const float* __restrict__ xeq1,
    float* __restrict__ xequ)
{
    __shared__ float wt[8][256];
    __shared__ float bs[8];
    const int tid = threadIdx.x;
    if (tid < 8) bs[tid] = b3[tid];
#pragma unroll
    for (int j = 0; j < 8; ++j)
        wt[j][tid] = W3[tid * 8 + j];
    __syncthreads();

    const int warp = tid >> 5, lane = tid & 31;
    const long row = (long)blockIdx.x * 8 + warp;
    const float* rp = r2 + row * 256;
    float acc[8] = {};
#pragma unroll
    for (int ii = 0; ii < 8; ++ii) {
        const int i = ii * 32 + lane;
        const float rv = rp[i];
#pragma unroll
        for (int j = 0; j < 8; ++j) acc[j] = fmaf(rv, wt[j][i], acc[j]);
    }
#pragma unroll
    for (int j = 0; j < 8; ++j)
#pragma unroll
        for (int o = 16; o; o >>= 1) acc[j] += __shfl_xor_sync(0xffffffffu, acc[j], o);
    if (lane == 0) {
        const long ob = row * 8;
#pragma unroll
        for (int j = 0; j < 8; ++j)
            xequ[ob + j] = xeq1[ob + j] + acc[j] + bs[j];
    }
}

__global__ void emit_kernel(const float* __restrict__ src, float* __restrict__ out,
                            long off, long n, long out_size, int mode) {
    const long i = (long)blockIdx.x * blockDim.x + threadIdx.x;
    if (i >= n) return;
    const long o = off + i;
    if (o >= out_size) return;
    out[o] = (mode == 0) ? src[i] : src[2 * i];
}

extern "C" void kernel_launch(void* const* d_in, const int* in_sizes, int n_in,
                              void* d_out, int out_size) {
    const float* x        = (const float*)d_in[0];
    const int*   snr      = (const int*)  d_in[1];
    const float* H_ri     = (const float*)d_in[2];
    const float* noise_ri = (const float*)d_in[3];
    const float* enc_W1 = (const float*)d_in[4];  const float* enc_b1 = (const float*)d_in[5];
    const float* enc_g1 = (const float*)d_in[6];  const float* enc_be1= (const float*)d_in[7];
    const float* enc_W2 = (const float*)d_in[8];  const float* enc_b2 = (const float*)d_in[9];
    const float* enc_g2 = (const float*)d_in[10]; const float* enc_be2= (const float*)d_in[11];
    const float* enc_W3 = (const float*)d_in[12]; const float* enc_b3 = (const float*)d_in[13];
    const float* dec_W1 = (const float*)d_in[14]; const float* dec_b1 = (const float*)d_in[15];
    const float* dec_g1 = (const float*)d_in[16]; const float* dec_be1= (const float*)d_in[17];
    const float* dec_W2 = (const float*)d_in[18]; const float* dec_b2 = (const float*)d_in[19];
    const float* dec_g2 = (const float*)d_in[20]; const float* dec_be2= (const float*)d_in[21];
    const float* dec_W3 = (const float*)d_in[22]; const float* dec_b3 = (const float*)d_in[23];
    const float* res_W1 = (const float*)d_in[24]; const float* res_b1 = (const float*)d_in[25];
    const float* res_W2 = (const float*)d_in[26]; const float* res_b2 = (const float*)d_in[27];
    const float* res_W3 = (const float*)d_in[28]; const float* res_b3 = (const float*)d_in[29];

    float *h1, *h2, *e, *hd1, *hd2, *HY, *r1, *r2;
    float *Ps, *ys, *xequs, *xeq1s, *sigs;
    float *W2e, *b2e, *W3e, *b3e, *W2d, *b2d, *W3d, *b3d, *part;
    cudaGetSymbolAddress((void**)&h1,  g_h1);
    cudaGetSymbolAddress((void**)&h2,  g_h2);
    cudaGetSymbolAddress((void**)&e,   g_e);
    cudaGetSymbolAddress((void**)&hd1, g_hd1);
    cudaGetSymbolAddress((void**)&hd2, g_hd2);
    cudaGetSymbolAddress((void**)&HY,  g_HY);
    cudaGetSymbolAddress((void**)&r1,  g_r1);
    cudaGetSymbolAddress((void**)&r2,  g_r2);
    cudaGetSymbolAddress((void**)&Ps,    g_P);
    cudaGetSymbolAddress((void**)&ys,    g_y);
    cudaGetSymbolAddress((void**)&xequs, g_xequ);
    cudaGetSymbolAddress((void**)&xeq1s, g_xeq1);
    cudaGetSymbolAddress((void**)&sigs,  g_sig);
    cudaGetSymbolAddress((void**)&W2e, g_W2e); cudaGetSymbolAddress((void**)&b2e, g_b2e);
    cudaGetSymbolAddress((void**)&W3e, g_W3e); cudaGetSymbolAddress((void**)&b3e, g_b3e);
    cudaGetSymbolAddress((void**)&W2d, g_W2d); cudaGetSymbolAddress((void**)&b2d, g_b2d);
    cudaGetSymbolAddress((void**)&W3d, g_W3d); cudaGetSymbolAddress((void**)&b3d, g_b3d);
    cudaGetSymbolAddress((void**)&part, g_part);

    // direct-to-output when layout matches (P | y | xequ | xeq1 | sig, interleaved-complex y)
    float* out = (float*)d_out;
    const long LP = 2097152, LY = 4194304, LX = 4194304, LS = 4194304;
    const long FULL = LP + LY + LX + LX + LS;
    const bool direct = ((long)out_size == FULL);
    float* P    = direct ? out                     : Ps;
    float* y    = direct ? out + LP                : ys;
    float* xequ = direct ? out + LP + LY           : xequs;
    float* xeq1 = direct ? out + LP + LY + LX      : xeq1s;
    float* sig  = direct ? out + LP + LY + LX + LX : sigs;

    const int SMB3 = (2 * (2 * AS_SZ) + 2 * (2 * BS_SZ)) * 4;  // 75776 B
    const int SMB1 = (2 * AS_SZ + 2 * BS_SZ) * 4;              // 37888 B
    cudaFuncSetAttribute(mma_gemm<3>, cudaFuncAttributeMaxDynamicSharedMemorySize, SMB3);
    cudaFuncSetAttribute(mma_gemm<1>, cudaFuncAttributeMaxDynamicSharedMemorySize, SMB1);

    prep_kernel<<<1, 1>>>(snr);

    // ---- encoder (3xTF32) ----
    mma_gemm<3><<<dim3(1, 64, 8), 512, SMB3>>>(x, 256, 32, enc_W1, 32 * 128, enc_b1, 128,
                                               h1, 1024, 128, 32, 128, 1);
    stats_kernel<<<dim3(8, 32), 128>>>(h1, 128, part);
    fuse_kernel<<<dim3(8, 8), 256>>>(enc_W2, enc_b2, enc_g1, enc_be1, 128, 128, W2e, b2e);
    mma_gemm<3><<<dim3(1, 64, 8), 512, SMB3>>>(h1, 1024, 128, W2e, 128 * 128, b2e, 128,
                                               h2, 1024, 128, 128, 128, 1);
    stats_kernel<<<dim3(8, 32), 128>>>(h2, 128, part);
    fuse_kernel<<<dim3(8, 8), 256>>>(enc_W3, enc_b3, enc_g2, enc_be2, 128, 512, W3e, b3e);
    mma_gemm<3><<<dim3(4, 64, 8), 512, SMB3>>>(h2, 1024, 128, W3e, 128 * 512, b3e, 512,
                                               e, 4096, 512, 128, 512, 0);
    combine_kernel<<<8192, 512>>>(sig);

    // ---- channel + MMSE ----
    channel_kernel<<<8192, 64>>>(H_ri, noise_ri, sig, y, xeq1);

    // ---- residual MLP (1xTF32) ----
    mma_gemm<1><<<dim3(2, 4096, 1), 512, SMB1>>>(HY, 40, 0, res_W1, 0, res_b1, 0,
                                                 r1, 256, 0, 40, 256, 1);
    mma_gemm<1><<<dim3(2, 4096, 1), 512, SMB1>>>(r1, 256, 0, res_W2, 0, res_b2, 0,
                                                 r2, 256, 0, 256, 256, 1);
    res3_add_kernel<<<65536, 256>>>(r2, res_W3, res_b3, xeq1, xequ);

    // ---- decoder: dec1 3x, dec2 1x, dec3 1x ----
    mma_gemm<3><<<dim3(2, 64, 8), 512, SMB3>>>(xequ, 512, 0, dec_W1, 512 * 256, dec_b1, 256,
                                               hd1, 2048, 256, 512, 256, 1);
    stats_kernel<<<dim3(8, 32), 256>>>(hd1, 256, part);
    fuse_kernel<<<dim3(8, 8), 256>>>(dec_W2, dec_b2, dec_g1, dec_be1, 256, 256, W2d, b2d);
    mma_gemm<1><<<dim3(2, 64, 8), 512, SMB1>>>(hd1, 2048, 256, W2d, 256 * 256, b2d, 256,
                                               hd2, 2048, 256, 256, 256, 1);
    stats_kernel<<<dim3(8, 32), 256>>>(hd2, 256, part);
    fuse_kernel<<<dim3(8, 8), 256>>>(dec_W3, dec_b3, dec_g2, dec_be2, 256, 32, W3d, b3d);
    mma_gemm<1><<<dim3(1, 64, 8), 512, SMB1>>>(hd2, 2048, 256, W3d, 256 * 32, b3d, 32,
                                               P, 256, 32, 256, 32, 0);

    // ---- fallback emission only if layout differs ----
    if (!direct) {
        const long osz = (long)out_size;
        auto emit = [&](const float* src, long off, long n, int mode) {
            if (off >= osz || n <= 0) return;
            long grid = (n + 255) / 256;
            emit_kernel<<<(unsigned)grid, 256>>>(src, out, off, n, osz, mode);
        };
        if (osz == LP + LY/2 + LX + LX + LS) {
            long off = 0;
            emit(P,    off, LP,   0); off += LP;
            emit(y,    off, LY/2, 1); off += LY/2;
            emit(xequ, off, LX,   0); off += LX;
            emit(xeq1, off, LX,   0); off += LX;
            emit(sig,  off, LS,   0);
        } else {
            long off = 0;
            emit(P,    off, LP, 0); off += LP;
            emit(y,    off, LY, 0); off += LY;
            emit(xequ, off, LX, 0); off += LX;
            emit(xeq1, off, LX, 0); off += LX;
            emit(sig,  off, LS, 0);
        }
    }
}